// round 1
// baseline (speedup 1.0000x reference)
#include <cuda_runtime.h>
#include <stdint.h>

#define N0   292864
#define N1V  11264
#define NBV  1024
#define FIN  602
#define FH   256
#define FOUT 41
#define E1V  281600
#define E2V  10240
#define WIN  19   // 32-bit words holding 602 bits
#define WSTR 20   // padded stride (word 19 == 0)
#define WH   8    // words for 256 bits
#define NPL  7    // bit planes (counts <= 127)

// ---------------- device scratch (static, allocation-free) ----------------
static __device__ __align__(16) uint32_t g_xb [(size_t)N0  * WSTR];      // 23.4 MB
static __device__ __align__(16) uint32_t g_pl1[(size_t)N1V * NPL * WSTR];// 6.3 MB
static __device__ int      g_PA1[N1V * NPL];
static __device__ __align__(16) uint32_t g_hb [N1V * WH];
static __device__ __align__(16) uint32_t g_pl2[NBV * NPL * WH];
static __device__ int      g_PA2[NBV * NPL];
static __device__ int g_deg1[N1V], g_off1[N1V + 1], g_cur1[N1V];
static __device__ int g_deg2[NBV], g_off2[NBV + 1], g_cur2[NBV];
static __device__ int g_csr1[E1V], g_csr2[E2V];
static __device__ unsigned char g_mask[N0];
static __device__ __align__(16) uint32_t g_wl1[FH * WSTR], g_wr1[FH * WSTR];
static __device__ float g_al1[FH], g_ar1[FH];
static __device__ int   g_ws1[FH];
static __device__ __align__(16) uint32_t g_wl2[FOUT * WH], g_wr2[FOUT * WH];
static __device__ float g_al2[FOUT], g_ar2[FOUT];
static __device__ int   g_ws2[FOUT];
static __device__ int g_is64;

// edge-index accessor: metadata may serialize int64 as int64 or (x64-off) int32
static __device__ __forceinline__ int eget(const void* p, long long i) {
    return g_is64 ? (int)((const long long*)p)[i] : ((const int*)p)[i];
}

// ---------------- kernels ----------------

__global__ void k_detect(const void* ei1) {
    if (blockIdx.x == 0 && threadIdx.x == 0) {
        const unsigned* u = (const unsigned*)ei1;
        int z = 0;
        for (int k = 0; k < 16; k++) z += (u[2 * k + 1] == 0u) ? 1 : 0;
        g_is64 = (z == 16) ? 1 : 0;   // int64 values < 2^31 -> high words all zero
    }
}

__global__ void k_zero() {
    int i = blockIdx.x * blockDim.x + threadIdx.x;
    if (i < N0)  g_mask[i] = 0;
    if (i < N1V) g_deg1[i] = 0;
    if (i < NBV) g_deg2[i] = 0;
}

__global__ void k_weights(const float* __restrict__ W1l, const float* __restrict__ W1r,
                          const float* __restrict__ W2l, const float* __restrict__ W2r) {
    int gw   = (blockIdx.x * blockDim.x + threadIdx.x) >> 5;
    int lane = threadIdx.x & 31;
    if (gw < 2 * FH) {
        const float* W  = (gw < FH) ? W1l : W1r;
        uint32_t*    WB = (gw < FH) ? g_wl1 : g_wr1;
        float*       AL = (gw < FH) ? g_al1 : g_ar1;
        int j = (gw < FH) ? gw : gw - FH;
        float asum = 0.f; int pos = 0;
        for (int k = 0; k < WIN; k++) {
            int f = k * 32 + lane;
            float w = (f < FIN) ? W[j * FIN + f] : 0.f;
            bool p = (f < FIN) && (w > 0.f);
            uint32_t b = __ballot_sync(0xffffffffu, p);
            if (lane == 0) WB[j * WSTR + k] = b;
            asum += fabsf(w);
            pos  += p ? 1 : 0;
        }
        if (lane == 0) WB[j * WSTR + WIN] = 0u;
        for (int o = 16; o; o >>= 1) asum += __shfl_xor_sync(0xffffffffu, asum, o);
        pos = __reduce_add_sync(0xffffffffu, pos);
        if (lane == 0) {
            AL[j] = asum / (float)FIN;
            if (gw < FH) g_ws1[j] = 2 * pos - FIN;
        }
    } else if (gw < 2 * FH + 2 * FOUT) {
        int g2 = gw - 2 * FH;
        const float* W  = (g2 < FOUT) ? W2l : W2r;
        uint32_t*    WB = (g2 < FOUT) ? g_wl2 : g_wr2;
        float*       AL = (g2 < FOUT) ? g_al2 : g_ar2;
        int j = (g2 < FOUT) ? g2 : g2 - FOUT;
        float asum = 0.f; int pos = 0;
        for (int k = 0; k < WH; k++) {
            int f = k * 32 + lane;
            float w = W[j * FH + f];
            bool p = (w > 0.f);
            uint32_t b = __ballot_sync(0xffffffffu, p);
            if (lane == 0) WB[j * WH + k] = b;
            asum += fabsf(w);
            pos  += p ? 1 : 0;
        }
        for (int o = 16; o; o >>= 1) asum += __shfl_xor_sync(0xffffffffu, asum, o);
        pos = __reduce_add_sync(0xffffffffu, pos);
        if (lane == 0) {
            AL[j] = asum / (float)FH;
            if (g2 < FOUT) g_ws2[j] = 2 * pos - FH;
        }
    }
}

__global__ void k_hist(const void* ei1, const void* ei2) {
    int e = blockIdx.x * blockDim.x + threadIdx.x;
    if (e < E1V) {
        int d = eget(ei1, (long long)E1V + e);
        atomicAdd(&g_deg1[d], 1);
        int s = eget(ei1, e);
        g_mask[s] = 1;
    }
    if (e < E2V) {
        int d = eget(ei2, (long long)E2V + e);
        atomicAdd(&g_deg2[d], 1);
    }
}

__global__ void k_scan1() {           // N1V = 1024 * 11
    __shared__ int sm[1024];
    int t = threadIdx.x;
    int loc[11]; int s = 0;
#pragma unroll
    for (int k = 0; k < 11; k++) { loc[k] = s; s += g_deg1[t * 11 + k]; }
    sm[t] = s; __syncthreads();
    for (int o = 1; o < 1024; o <<= 1) {
        int v = (t >= o) ? sm[t - o] : 0; __syncthreads();
        sm[t] += v; __syncthreads();
    }
    int ex = (t > 0) ? sm[t - 1] : 0;
#pragma unroll
    for (int k = 0; k < 11; k++) {
        g_off1[t * 11 + k] = ex + loc[k];
        g_cur1[t * 11 + k] = ex + loc[k];
    }
    if (t == 1023) g_off1[N1V] = sm[1023];
}

__global__ void k_scan2() {           // NBV = 1024
    __shared__ int sm[1024];
    int t = threadIdx.x;
    int s = g_deg2[t];
    sm[t] = s; __syncthreads();
    for (int o = 1; o < 1024; o <<= 1) {
        int v = (t >= o) ? sm[t - o] : 0; __syncthreads();
        sm[t] += v; __syncthreads();
    }
    int ex = (t > 0) ? sm[t - 1] : 0;
    g_off2[t] = ex; g_cur2[t] = ex;
    if (t == 1023) g_off2[NBV] = sm[1023];
}

__global__ void k_scatter(const void* ei1, const void* ei2) {
    int e = blockIdx.x * blockDim.x + threadIdx.x;
    if (e < E1V) {
        int d = eget(ei1, (long long)E1V + e);
        int s = eget(ei1, e);
        int p = atomicAdd(&g_cur1[d], 1);
        g_csr1[p] = s;
    }
    if (e < E2V) {
        int d = eget(ei2, (long long)E2V + e);
        int s = eget(ei2, e);
        int p = atomicAdd(&g_cur2[d], 1);
        g_csr2[p] = s;
    }
}

// per-row mean + sign + bitpack; skip rows never used downstream
__global__ __launch_bounds__(256) void k_bin(const float* __restrict__ x) {
    int wid = threadIdx.x >> 5, lane = threadIdx.x & 31;
    int row = blockIdx.x * 8 + wid;
    bool need = (row < N1V) || (g_mask[row] != 0);
    if (!need) return;
    const float* xr = x + (size_t)row * FIN;
    float v[WIN]; float s = 0.f;
#pragma unroll
    for (int k = 0; k < WIN; k++) {
        int f = k * 32 + lane;
        float val = (f < FIN) ? xr[f] : 0.f;
        v[k] = val; s += val;
    }
    for (int o = 16; o; o >>= 1) s += __shfl_xor_sync(0xffffffffu, s, o);
    float mean = s * (1.f / (float)FIN);
    uint32_t myw = 0;
#pragma unroll
    for (int k = 0; k < WIN; k++) {
        uint32_t b = __ballot_sync(0xffffffffu, ((k * 32 + lane) < FIN) && (v[k] > mean));
        if (lane == k) myw = b;
    }
    if (lane < WSTR) g_xb[(size_t)row * WSTR + lane] = (lane < WIN) ? myw : 0u;
}

// bit-sliced (ripple-carry) per-feature edge-count accumulation, layer 1
__global__ __launch_bounds__(256) void k_agg1() {
    int gw   = (blockIdx.x * blockDim.x + threadIdx.x) >> 5;
    int lane = threadIdx.x & 31;
    if (gw >= N1V) return;
    int beg = g_off1[gw], d = g_deg1[gw];
    uint32_t p0 = 0, p1 = 0, p2 = 0, p3 = 0, p4 = 0, p5 = 0, p6 = 0;
    for (int e = 0; e < d; e++) {
        int s = g_csr1[beg + e];
        uint32_t c = (lane < WSTR) ? g_xb[(size_t)s * WSTR + lane] : 0u;
        uint32_t t;
        t = p0 & c; p0 ^= c; c = t;
        t = p1 & c; p1 ^= c; c = t;
        t = p2 & c; p2 ^= c; c = t;
        t = p3 & c; p3 ^= c; c = t;
        t = p4 & c; p4 ^= c; c = t;
        t = p5 & c; p5 ^= c; c = t;
        p6 ^= c;
    }
    size_t base = (size_t)gw * NPL * WSTR;
    if (lane < WSTR) {
        g_pl1[base + 0 * WSTR + lane] = p0;
        g_pl1[base + 1 * WSTR + lane] = p1;
        g_pl1[base + 2 * WSTR + lane] = p2;
        g_pl1[base + 3 * WSTR + lane] = p3;
        g_pl1[base + 4 * WSTR + lane] = p4;
        g_pl1[base + 5 * WSTR + lane] = p5;
        g_pl1[base + 6 * WSTR + lane] = p6;
    }
    int pa;
    pa = __reduce_add_sync(0xffffffffu, __popc(p0)); if (!lane) g_PA1[gw * NPL + 0] = pa;
    pa = __reduce_add_sync(0xffffffffu, __popc(p1)); if (!lane) g_PA1[gw * NPL + 1] = pa;
    pa = __reduce_add_sync(0xffffffffu, __popc(p2)); if (!lane) g_PA1[gw * NPL + 2] = pa;
    pa = __reduce_add_sync(0xffffffffu, __popc(p3)); if (!lane) g_PA1[gw * NPL + 3] = pa;
    pa = __reduce_add_sync(0xffffffffu, __popc(p4)); if (!lane) g_PA1[gw * NPL + 4] = pa;
    pa = __reduce_add_sync(0xffffffffu, __popc(p5)); if (!lane) g_PA1[gw * NPL + 5] = pa;
    pa = __reduce_add_sync(0xffffffffu, __popc(p6)); if (!lane) g_PA1[gw * NPL + 6] = pa;
}

#define RPB1 16
// layer-1 popcount GEMM + bias + relu + row-mean binarize -> g_hb
__global__ __launch_bounds__(256) void k_gemm1(const float* __restrict__ b1) {
    int tid = threadIdx.x, lane = tid & 31, wid = tid >> 5;
    __shared__ __align__(16) uint32_t sa[NPL * WSTR];
    __shared__ __align__(16) uint32_t sx[WSTR];
    __shared__ int sPA[NPL];
    __shared__ int scnt;
    __shared__ float sred[8];

    uint4 wl4[5], wr4[5];
    const uint4* wlp = (const uint4*)&g_wl1[tid * WSTR];
    const uint4* wrp = (const uint4*)&g_wr1[tid * WSTR];
#pragma unroll
    for (int q = 0; q < 5; q++) { wl4[q] = wlp[q]; wr4[q] = wrp[q]; }
    float al = g_al1[tid], ar = g_ar1[tid], bb = b1[tid];
    int wsum = g_ws1[tid];

    for (int r = 0; r < RPB1; r++) {
        int i = blockIdx.x * RPB1 + r;
        for (int idx = tid; idx < NPL * WSTR; idx += 256)
            sa[idx] = g_pl1[(size_t)i * NPL * WSTR + idx];
        if (tid < WSTR) sx[tid] = g_xb[(size_t)i * WSTR + tid];
        if (tid < NPL)  sPA[tid] = g_PA1[i * NPL + tid];
        if (tid == 255) scnt = g_deg1[i];
        __syncthreads();

        int cnt = scnt;
        int np = (cnt > 0) ? (32 - __clz(cnt)) : 0;
        int CW = 0;
        for (int p = 0; p < np; p++) {
            const uint4* ap = (const uint4*)&sa[p * WSTR];
            int s = 0;
#pragma unroll
            for (int q = 0; q < 5; q++) {
                uint4 a = ap[q]; uint4 w = wl4[q];
                s += __popc(a.x & w.x) + __popc(a.y & w.y) +
                     __popc(a.z & w.z) + __popc(a.w & w.w);
            }
            CW += (2 * s - sPA[p]) * (1 << p);
        }
        int x2 = 0;
        const uint4* xp = (const uint4*)sx;
#pragma unroll
        for (int q = 0; q < 5; q++) {
            uint4 a = xp[q]; uint4 w = wr4[q];
            x2 += __popc(a.x ^ w.x) + __popc(a.y ^ w.y) +
                  __popc(a.z ^ w.z) + __popc(a.w ^ w.w);
        }
        int dot2 = FIN - 2 * x2;
        float rc = (cnt > 0) ? (1.f / (float)cnt) : 1.f;
        float h = (float)(2 * CW - cnt * wsum) * rc * al + (float)dot2 * ar + bb;
        h = fmaxf(h, 0.f);

        float s2 = h;
        for (int o = 16; o; o >>= 1) s2 += __shfl_xor_sync(0xffffffffu, s2, o);
        if (lane == 0) sred[wid] = s2;
        __syncthreads();
        float tot = 0.f;
#pragma unroll
        for (int k = 0; k < 8; k++) tot += sred[k];
        float mean = tot * (1.f / (float)FH);
        uint32_t bits = __ballot_sync(0xffffffffu, h > mean);
        if (lane == 0) g_hb[i * WH + wid] = bits;
        __syncthreads();
    }
}

__global__ __launch_bounds__(256) void k_agg2() {
    int gw   = (blockIdx.x * blockDim.x + threadIdx.x) >> 5;
    int lane = threadIdx.x & 31;
    if (gw >= NBV) return;
    int beg = g_off2[gw], d = g_deg2[gw];
    uint32_t p0 = 0, p1 = 0, p2 = 0, p3 = 0, p4 = 0, p5 = 0, p6 = 0;
    for (int e = 0; e < d; e++) {
        int s = g_csr2[beg + e];
        uint32_t c = (lane < WH) ? g_hb[(size_t)s * WH + lane] : 0u;
        uint32_t t;
        t = p0 & c; p0 ^= c; c = t;
        t = p1 & c; p1 ^= c; c = t;
        t = p2 & c; p2 ^= c; c = t;
        t = p3 & c; p3 ^= c; c = t;
        t = p4 & c; p4 ^= c; c = t;
        t = p5 & c; p5 ^= c; c = t;
        p6 ^= c;
    }
    size_t base = (size_t)gw * NPL * WH;
    if (lane < WH) {
        g_pl2[base + 0 * WH + lane] = p0;
        g_pl2[base + 1 * WH + lane] = p1;
        g_pl2[base + 2 * WH + lane] = p2;
        g_pl2[base + 3 * WH + lane] = p3;
        g_pl2[base + 4 * WH + lane] = p4;
        g_pl2[base + 5 * WH + lane] = p5;
        g_pl2[base + 6 * WH + lane] = p6;
    }
    int pa;
    pa = __reduce_add_sync(0xffffffffu, __popc(p0)); if (!lane) g_PA2[gw * NPL + 0] = pa;
    pa = __reduce_add_sync(0xffffffffu, __popc(p1)); if (!lane) g_PA2[gw * NPL + 1] = pa;
    pa = __reduce_add_sync(0xffffffffu, __popc(p2)); if (!lane) g_PA2[gw * NPL + 2] = pa;
    pa = __reduce_add_sync(0xffffffffu, __popc(p3)); if (!lane) g_PA2[gw * NPL + 3] = pa;
    pa = __reduce_add_sync(0xffffffffu, __popc(p4)); if (!lane) g_PA2[gw * NPL + 4] = pa;
    pa = __reduce_add_sync(0xffffffffu, __popc(p5)); if (!lane) g_PA2[gw * NPL + 5] = pa;
    pa = __reduce_add_sync(0xffffffffu, __popc(p6)); if (!lane) g_PA2[gw * NPL + 6] = pa;
}

// layer-2 popcount GEMM + bias + log_softmax -> output
__global__ __launch_bounds__(64) void k_gemm2(const float* __restrict__ b2,
                                              float* __restrict__ out) {
    int i = blockIdx.x, tid = threadIdx.x;
    __shared__ __align__(16) uint32_t sa[NPL * WH];
    __shared__ __align__(16) uint32_t sx[WH];
    __shared__ int sPA[NPL];
    __shared__ int scnt;
    __shared__ float vals[FOUT];
    __shared__ float slse;

    if (tid < NPL * WH) sa[tid] = g_pl2[(size_t)i * NPL * WH + tid];
    if (tid < WH)  sx[tid]  = g_hb[(size_t)i * WH + tid];
    if (tid < NPL) sPA[tid] = g_PA2[i * NPL + tid];
    if (tid == 63) scnt = g_deg2[i];
    __syncthreads();

    if (tid < FOUT) {
        int j = tid;
        const uint4* wlp = (const uint4*)&g_wl2[j * WH];
        const uint4* wrp = (const uint4*)&g_wr2[j * WH];
        uint4 wlA = wlp[0], wlB = wlp[1];
        uint4 wrA = wrp[0], wrB = wrp[1];
        int cnt = scnt;
        int np = (cnt > 0) ? (32 - __clz(cnt)) : 0;
        int CW = 0;
        for (int p = 0; p < np; p++) {
            const uint4* ap = (const uint4*)&sa[p * WH];
            uint4 aA = ap[0], aB = ap[1];
            int s = __popc(aA.x & wlA.x) + __popc(aA.y & wlA.y) +
                    __popc(aA.z & wlA.z) + __popc(aA.w & wlA.w) +
                    __popc(aB.x & wlB.x) + __popc(aB.y & wlB.y) +
                    __popc(aB.z & wlB.z) + __popc(aB.w & wlB.w);
            CW += (2 * s - sPA[p]) * (1 << p);
        }
        const uint4* xp = (const uint4*)sx;
        uint4 xA = xp[0], xB = xp[1];
        int x2 = __popc(xA.x ^ wrA.x) + __popc(xA.y ^ wrA.y) +
                 __popc(xA.z ^ wrA.z) + __popc(xA.w ^ wrA.w) +
                 __popc(xB.x ^ wrB.x) + __popc(xB.y ^ wrB.y) +
                 __popc(xB.z ^ wrB.z) + __popc(xB.w ^ wrB.w);
        int dot2 = FH - 2 * x2;
        float rc = (cnt > 0) ? (1.f / (float)cnt) : 1.f;
        float v = (float)(2 * CW - cnt * g_ws2[j]) * rc * g_al2[j]
                + (float)dot2 * g_ar2[j] + b2[j];
        vals[j] = v;
    }
    __syncthreads();
    if (tid == 0) {
        float m = vals[0];
        for (int k = 1; k < FOUT; k++) m = fmaxf(m, vals[k]);
        float se = 0.f;
        for (int k = 0; k < FOUT; k++) se += expf(vals[k] - m);
        slse = m + logf(se);
    }
    __syncthreads();
    if (tid < FOUT) out[i * FOUT + tid] = vals[tid] - slse;
}

// ---------------- host launcher ----------------
extern "C" void kernel_launch(void* const* d_in, const int* in_sizes, int n_in,
                              void* d_out, int out_size) {
    const float* x = nullptr;
    const void *ei1 = nullptr, *ei2 = nullptr;
    const float *W1l = nullptr, *W1r = nullptr, *b1 = nullptr;
    const float *W2l = nullptr, *W2r = nullptr, *b2 = nullptr;
    int c1 = 0, c2 = 0;
    for (int i = 0; i < n_in; i++) {
        switch (in_sizes[i]) {
            case 176304128: x   = (const float*)d_in[i]; break;
            case 563200:    ei1 = d_in[i]; break;
            case 20480:     ei2 = d_in[i]; break;
            case 154112:    if (c1++ == 0) W1l = (const float*)d_in[i];
                            else           W1r = (const float*)d_in[i]; break;
            case 256:       b1  = (const float*)d_in[i]; break;
            case 10496:     if (c2++ == 0) W2l = (const float*)d_in[i];
                            else           W2r = (const float*)d_in[i]; break;
            case 41:        b2  = (const float*)d_in[i]; break;
            default: break; // n1 / n_batch scalars
        }
    }

    k_detect<<<1, 32>>>(ei1);
    k_zero<<<(N0 + 255) / 256, 256>>>();
    k_weights<<<75, 256>>>(W1l, W1r, W2l, W2r);
    k_hist<<<(E1V + 255) / 256, 256>>>(ei1, ei2);
    k_scan1<<<1, 1024>>>();
    k_scan2<<<1, 1024>>>();
    k_scatter<<<(E1V + 255) / 256, 256>>>(ei1, ei2);
    k_bin<<<N0 / 8, 256>>>(x);
    k_agg1<<<N1V / 8, 256>>>();
    k_gemm1<<<N1V / RPB1, 256>>>(b1);
    k_agg2<<<NBV / 8, 256>>>();
    k_gemm2<<<NBV, 64>>>(b2, (float*)d_out);
}

// round 4
// speedup vs baseline: 1.1148x; 1.1148x over previous
#include <cuda_runtime.h>
#include <stdint.h>

#define N0   292864
#define N1V  11264
#define NBV  1024
#define FIN  602
#define FH   256
#define FOUT 41
#define E1V  281600
#define E2V  10240
#define WIN  19   // 32-bit words holding 602 bits
#define WSTR 20   // padded stride (word 19 == 0)
#define WH   8    // words for 256 bits
#define NPL  7    // bit planes (counts <= 127)

// ---------------- device scratch (static, allocation-free) ----------------
static __device__ __align__(16) uint32_t g_xb [(size_t)N0  * WSTR];      // 23.4 MB
static __device__ __align__(16) uint32_t g_pl1[(size_t)N1V * NPL * WSTR];// 6.3 MB
static __device__ int      g_PA1[N1V * NPL];
static __device__ __align__(16) uint32_t g_hb [N1V * WH];
static __device__ int g_deg1[N1V], g_off1[N1V + 1], g_cur1[N1V];
static __device__ int g_deg2[NBV], g_off2[NBV + 1], g_cur2[NBV];
static __device__ int g_csr1[E1V], g_csr2[E2V];
static __device__ unsigned char g_mask[N0];   // zero-init at load; hist only sets 1s (idempotent)
static __device__ __align__(16) uint32_t g_wl1[FH * WSTR], g_wr1[FH * WSTR];
static __device__ float g_al1[FH], g_ar1[FH];
static __device__ int   g_ws1[FH];
static __device__ __align__(16) uint32_t g_wl2[FOUT * WH], g_wr2[FOUT * WH];
static __device__ float g_al2[FOUT], g_ar2[FOUT];
static __device__ int   g_ws2[FOUT];
static __device__ int g_is64;

// edge-index accessor: metadata may serialize int64 as int64 or (x64-off) int32
static __device__ __forceinline__ int eget(const void* p, long long i) {
    return g_is64 ? (int)((const long long*)p)[i] : ((const int*)p)[i];
}

// ripple-carry add of a 1-bit addend into 7 bit-planes
#define RIPPLE(c) do { uint32_t t_;            \
    t_ = p0 & (c); p0 ^= (c); (c) = t_;        \
    t_ = p1 & (c); p1 ^= (c); (c) = t_;        \
    t_ = p2 & (c); p2 ^= (c); (c) = t_;        \
    t_ = p3 & (c); p3 ^= (c); (c) = t_;        \
    t_ = p4 & (c); p4 ^= (c); (c) = t_;        \
    t_ = p5 & (c); p5 ^= (c); (c) = t_;        \
    p6 ^= (c); } while (0)

// ---------------- kernels ----------------

// zero degree arrays + detect edge dtype (mask needs no zeroing: zero-init + idempotent)
__global__ void k_init(const void* ei1) {
    int i = blockIdx.x * blockDim.x + threadIdx.x;
    if (i < N1V) g_deg1[i] = 0;
    if (i < NBV) g_deg2[i] = 0;
    if (i == 0) {
        const unsigned* u = (const unsigned*)ei1;
        int z = 0;
        for (int k = 0; k < 16; k++) z += (u[2 * k + 1] == 0u) ? 1 : 0;
        g_is64 = (z == 16) ? 1 : 0;   // int64 values < 2^31 -> high words all zero
    }
}

__global__ void k_hist(const void* ei1, const void* ei2) {
    int e = blockIdx.x * blockDim.x + threadIdx.x;
    if (e < E1V) {
        int d = eget(ei1, (long long)E1V + e);
        atomicAdd(&g_deg1[d], 1);
        int s = eget(ei1, e);
        g_mask[s] = 1;
    }
    if (e < E2V) {
        int d = eget(ei2, (long long)E2V + e);
        atomicAdd(&g_deg2[d], 1);
    }
}

__global__ void k_weights(const float* __restrict__ W1l, const float* __restrict__ W1r,
                          const float* __restrict__ W2l, const float* __restrict__ W2r) {
    int gw   = (blockIdx.x * blockDim.x + threadIdx.x) >> 5;
    int lane = threadIdx.x & 31;
    if (gw < 2 * FH) {
        const float* W  = (gw < FH) ? W1l : W1r;
        uint32_t*    WB = (gw < FH) ? g_wl1 : g_wr1;
        float*       AL = (gw < FH) ? g_al1 : g_ar1;
        int j = (gw < FH) ? gw : gw - FH;
        float asum = 0.f; int pos = 0;
        for (int k = 0; k < WIN; k++) {
            int f = k * 32 + lane;
            float w = (f < FIN) ? W[j * FIN + f] : 0.f;
            bool p = (f < FIN) && (w > 0.f);
            uint32_t b = __ballot_sync(0xffffffffu, p);
            if (lane == 0) WB[j * WSTR + k] = b;
            asum += fabsf(w);
            pos  += p ? 1 : 0;
        }
        if (lane == 0) WB[j * WSTR + WIN] = 0u;
        for (int o = 16; o; o >>= 1) asum += __shfl_xor_sync(0xffffffffu, asum, o);
        pos = __reduce_add_sync(0xffffffffu, pos);
        if (lane == 0) {
            AL[j] = asum / (float)FIN;
            if (gw < FH) g_ws1[j] = 2 * pos - FIN;
        }
    } else if (gw < 2 * FH + 2 * FOUT) {
        int g2 = gw - 2 * FH;
        const float* W  = (g2 < FOUT) ? W2l : W2r;
        uint32_t*    WB = (g2 < FOUT) ? g_wl2 : g_wr2;
        float*       AL = (g2 < FOUT) ? g_al2 : g_ar2;
        int j = (g2 < FOUT) ? g2 : g2 - FOUT;
        float asum = 0.f; int pos = 0;
        for (int k = 0; k < WH; k++) {
            int f = k * 32 + lane;
            float w = W[j * FH + f];
            bool p = (w > 0.f);
            uint32_t b = __ballot_sync(0xffffffffu, p);
            if (lane == 0) WB[j * WH + k] = b;
            asum += fabsf(w);
            pos  += p ? 1 : 0;
        }
        for (int o = 16; o; o >>= 1) asum += __shfl_xor_sync(0xffffffffu, asum, o);
        pos = __reduce_add_sync(0xffffffffu, pos);
        if (lane == 0) {
            AL[j] = asum / (float)FH;
            if (g2 < FOUT) g_ws2[j] = 2 * pos - FH;
        }
    }
}

// per-row mean + sign + bitpack; skip rows never used downstream.
// __ldcs: x is single-use streaming data -> don't evict g_xb from L2.
__global__ __launch_bounds__(256) void k_bin(const float* __restrict__ x) {
    int wid = threadIdx.x >> 5, lane = threadIdx.x & 31;
    int row = blockIdx.x * 8 + wid;
    bool need = (row < N1V) || (g_mask[row] != 0);
    if (!need) return;
    const float* xr = x + (size_t)row * FIN;
    float v[WIN]; float s = 0.f;
#pragma unroll
    for (int k = 0; k < WIN; k++) {
        int f = k * 32 + lane;
        float val = (f < FIN) ? __ldcs(xr + f) : 0.f;
        v[k] = val; s += val;
    }
    for (int o = 16; o; o >>= 1) s += __shfl_xor_sync(0xffffffffu, s, o);
    float mean = s * (1.f / (float)FIN);
    uint32_t myw = 0;
#pragma unroll
    for (int k = 0; k < WIN; k++) {
        uint32_t b = __ballot_sync(0xffffffffu, ((k * 32 + lane) < FIN) && (v[k] > mean));
        if (lane == k) myw = b;
    }
    if (lane < WSTR) g_xb[(size_t)row * WSTR + lane] = (lane < WIN) ? myw : 0u;
}

// both prefix scans in one launch (block 0: layer1, block 1: layer2)
__global__ void k_scan() {
    __shared__ int sm[1024];
    int t = threadIdx.x;
    if (blockIdx.x == 0) {                 // N1V = 1024 * 11
        int loc[11]; int s = 0;
#pragma unroll
        for (int k = 0; k < 11; k++) { loc[k] = s; s += g_deg1[t * 11 + k]; }
        sm[t] = s; __syncthreads();
        for (int o = 1; o < 1024; o <<= 1) {
            int v = (t >= o) ? sm[t - o] : 0; __syncthreads();
            sm[t] += v; __syncthreads();
        }
        int ex = (t > 0) ? sm[t - 1] : 0;
#pragma unroll
        for (int k = 0; k < 11; k++) {
            g_off1[t * 11 + k] = ex + loc[k];
            g_cur1[t * 11 + k] = ex + loc[k];
        }
        if (t == 1023) g_off1[N1V] = sm[1023];
    } else {                               // NBV = 1024
        int s = g_deg2[t];
        sm[t] = s; __syncthreads();
        for (int o = 1; o < 1024; o <<= 1) {
            int v = (t >= o) ? sm[t - o] : 0; __syncthreads();
            sm[t] += v; __syncthreads();
        }
        int ex = (t > 0) ? sm[t - 1] : 0;
        g_off2[t] = ex; g_cur2[t] = ex;
        if (t == 1023) g_off2[NBV] = sm[1023];
    }
}

__global__ void k_scatter(const void* ei1, const void* ei2) {
    int e = blockIdx.x * blockDim.x + threadIdx.x;
    if (e < E1V) {
        int d = eget(ei1, (long long)E1V + e);
        int s = eget(ei1, e);
        int p = atomicAdd(&g_cur1[d], 1);
        g_csr1[p] = s;
    }
    if (e < E2V) {
        int d = eget(ei2, (long long)E2V + e);
        int s = eget(ei2, e);
        int p = atomicAdd(&g_cur2[d], 1);
        g_csr2[p] = s;
    }
}

// bit-sliced (ripple-carry) per-feature edge-count accumulation, layer 1
// 4x edge unroll: 4 independent gathers in flight per warp
__global__ __launch_bounds__(256) void k_agg1() {
    int gw   = (blockIdx.x * blockDim.x + threadIdx.x) >> 5;
    int lane = threadIdx.x & 31;
    if (gw >= N1V) return;
    int beg = g_off1[gw], d = g_deg1[gw];
    uint32_t p0 = 0, p1 = 0, p2 = 0, p3 = 0, p4 = 0, p5 = 0, p6 = 0;
    bool act = (lane < WSTR);
    int e = 0;
    for (; e + 4 <= d; e += 4) {
        int s0 = __ldg(&g_csr1[beg + e + 0]);
        int s1 = __ldg(&g_csr1[beg + e + 1]);
        int s2 = __ldg(&g_csr1[beg + e + 2]);
        int s3 = __ldg(&g_csr1[beg + e + 3]);
        uint32_t c0 = act ? __ldg(&g_xb[(size_t)s0 * WSTR + lane]) : 0u;
        uint32_t c1 = act ? __ldg(&g_xb[(size_t)s1 * WSTR + lane]) : 0u;
        uint32_t c2 = act ? __ldg(&g_xb[(size_t)s2 * WSTR + lane]) : 0u;
        uint32_t c3 = act ? __ldg(&g_xb[(size_t)s3 * WSTR + lane]) : 0u;
        RIPPLE(c0); RIPPLE(c1); RIPPLE(c2); RIPPLE(c3);
    }
    for (; e < d; e++) {
        int s = __ldg(&g_csr1[beg + e]);
        uint32_t c = act ? __ldg(&g_xb[(size_t)s * WSTR + lane]) : 0u;
        RIPPLE(c);
    }
    size_t base = (size_t)gw * NPL * WSTR;
    if (act) {
        g_pl1[base + 0 * WSTR + lane] = p0;
        g_pl1[base + 1 * WSTR + lane] = p1;
        g_pl1[base + 2 * WSTR + lane] = p2;
        g_pl1[base + 3 * WSTR + lane] = p3;
        g_pl1[base + 4 * WSTR + lane] = p4;
        g_pl1[base + 5 * WSTR + lane] = p5;
        g_pl1[base + 6 * WSTR + lane] = p6;
    }
    int pa;
    pa = __reduce_add_sync(0xffffffffu, __popc(p0)); if (!lane) g_PA1[gw * NPL + 0] = pa;
    pa = __reduce_add_sync(0xffffffffu, __popc(p1)); if (!lane) g_PA1[gw * NPL + 1] = pa;
    pa = __reduce_add_sync(0xffffffffu, __popc(p2)); if (!lane) g_PA1[gw * NPL + 2] = pa;
    pa = __reduce_add_sync(0xffffffffu, __popc(p3)); if (!lane) g_PA1[gw * NPL + 3] = pa;
    pa = __reduce_add_sync(0xffffffffu, __popc(p4)); if (!lane) g_PA1[gw * NPL + 4] = pa;
    pa = __reduce_add_sync(0xffffffffu, __popc(p5)); if (!lane) g_PA1[gw * NPL + 5] = pa;
    pa = __reduce_add_sync(0xffffffffu, __popc(p6)); if (!lane) g_PA1[gw * NPL + 6] = pa;
}

#define RPB1 16
// layer-1 popcount GEMM + bias + relu + row-mean binarize -> g_hb
__global__ __launch_bounds__(256) void k_gemm1(const float* __restrict__ b1) {
    int tid = threadIdx.x, lane = tid & 31, wid = tid >> 5;
    __shared__ __align__(16) uint32_t sa[NPL * WSTR];
    __shared__ __align__(16) uint32_t sx[WSTR];
    __shared__ int sPA[NPL];
    __shared__ int scnt;
    __shared__ float sred[8];

    uint4 wl4[5], wr4[5];
    const uint4* wlp = (const uint4*)&g_wl1[tid * WSTR];
    const uint4* wrp = (const uint4*)&g_wr1[tid * WSTR];
#pragma unroll
    for (int q = 0; q < 5; q++) { wl4[q] = wlp[q]; wr4[q] = wrp[q]; }
    float al = g_al1[tid], ar = g_ar1[tid], bb = b1[tid];
    int wsum = g_ws1[tid];

    for (int r = 0; r < RPB1; r++) {
        int i = blockIdx.x * RPB1 + r;
        for (int idx = tid; idx < NPL * WSTR; idx += 256)
            sa[idx] = g_pl1[(size_t)i * NPL * WSTR + idx];
        if (tid < WSTR) sx[tid] = g_xb[(size_t)i * WSTR + tid];
        if (tid < NPL)  sPA[tid] = g_PA1[i * NPL + tid];
        if (tid == 255) scnt = g_deg1[i];
        __syncthreads();

        int cnt = scnt;
        int np = (cnt > 0) ? (32 - __clz(cnt)) : 0;
        int CW = 0;
        for (int p = 0; p < np; p++) {
            const uint4* ap = (const uint4*)&sa[p * WSTR];
            int s = 0;
#pragma unroll
            for (int q = 0; q < 5; q++) {
                uint4 a = ap[q]; uint4 w = wl4[q];
                s += __popc(a.x & w.x) + __popc(a.y & w.y) +
                     __popc(a.z & w.z) + __popc(a.w & w.w);
            }
            CW += (2 * s - sPA[p]) * (1 << p);
        }
        int x2 = 0;
        const uint4* xp = (const uint4*)sx;
#pragma unroll
        for (int q = 0; q < 5; q++) {
            uint4 a = xp[q]; uint4 w = wr4[q];
            x2 += __popc(a.x ^ w.x) + __popc(a.y ^ w.y) +
                  __popc(a.z ^ w.z) + __popc(a.w ^ w.w);
        }
        int dot2 = FIN - 2 * x2;
        float rc = (cnt > 0) ? (1.f / (float)cnt) : 1.f;
        float h = (float)(2 * CW - cnt * wsum) * rc * al + (float)dot2 * ar + bb;
        h = fmaxf(h, 0.f);

        float s2 = h;
        for (int o = 16; o; o >>= 1) s2 += __shfl_xor_sync(0xffffffffu, s2, o);
        if (lane == 0) sred[wid] = s2;
        __syncthreads();
        float tot = 0.f;
#pragma unroll
        for (int k = 0; k < 8; k++) tot += sred[k];
        float mean = tot * (1.f / (float)FH);
        uint32_t bits = __ballot_sync(0xffffffffu, h > mean);
        if (lane == 0) g_hb[i * WH + wid] = bits;
        __syncthreads();
    }
}

// fused layer 2: warp 0 aggregates edges (bit-sliced), then 64 threads do
// popcount GEMM + bias + log_softmax. One block per target row.
__global__ __launch_bounds__(64) void k_l2(const float* __restrict__ b2,
                                           float* __restrict__ out) {
    int i = blockIdx.x, tid = threadIdx.x;
    __shared__ __align__(16) uint32_t sa[NPL * WH];
    __shared__ __align__(16) uint32_t sx[WH];
    __shared__ int sPA[NPL];
    __shared__ float vals[FOUT];
    __shared__ float slse;

    int cnt = g_deg2[i];
    if (tid < WH) sx[tid] = g_hb[(size_t)i * WH + tid];

    if (tid < 32) {               // warp 0: bit-sliced aggregation
        int lane = tid;
        int beg = g_off2[i];
        uint32_t p0 = 0, p1 = 0, p2 = 0, p3 = 0, p4 = 0, p5 = 0, p6 = 0;
        bool act = (lane < WH);
        int e = 0;
        for (; e + 4 <= cnt; e += 4) {
            int s0 = __ldg(&g_csr2[beg + e + 0]);
            int s1 = __ldg(&g_csr2[beg + e + 1]);
            int s2 = __ldg(&g_csr2[beg + e + 2]);
            int s3 = __ldg(&g_csr2[beg + e + 3]);
            uint32_t c0 = act ? __ldg(&g_hb[(size_t)s0 * WH + lane]) : 0u;
            uint32_t c1 = act ? __ldg(&g_hb[(size_t)s1 * WH + lane]) : 0u;
            uint32_t c2 = act ? __ldg(&g_hb[(size_t)s2 * WH + lane]) : 0u;
            uint32_t c3 = act ? __ldg(&g_hb[(size_t)s3 * WH + lane]) : 0u;
            RIPPLE(c0); RIPPLE(c1); RIPPLE(c2); RIPPLE(c3);
        }
        for (; e < cnt; e++) {
            int s = __ldg(&g_csr2[beg + e]);
            uint32_t c = act ? __ldg(&g_hb[(size_t)s * WH + lane]) : 0u;
            RIPPLE(c);
        }
        if (act) {
            sa[0 * WH + lane] = p0; sa[1 * WH + lane] = p1;
            sa[2 * WH + lane] = p2; sa[3 * WH + lane] = p3;
            sa[4 * WH + lane] = p4; sa[5 * WH + lane] = p5;
            sa[6 * WH + lane] = p6;
        }
        int pa;
        pa = __reduce_add_sync(0xffffffffu, __popc(p0)); if (!lane) sPA[0] = pa;
        pa = __reduce_add_sync(0xffffffffu, __popc(p1)); if (!lane) sPA[1] = pa;
        pa = __reduce_add_sync(0xffffffffu, __popc(p2)); if (!lane) sPA[2] = pa;
        pa = __reduce_add_sync(0xffffffffu, __popc(p3)); if (!lane) sPA[3] = pa;
        pa = __reduce_add_sync(0xffffffffu, __popc(p4)); if (!lane) sPA[4] = pa;
        pa = __reduce_add_sync(0xffffffffu, __popc(p5)); if (!lane) sPA[5] = pa;
        pa = __reduce_add_sync(0xffffffffu, __popc(p6)); if (!lane) sPA[6] = pa;
    }
    __syncthreads();

    if (tid < FOUT) {
        int j = tid;
        const uint4* wlp = (const uint4*)&g_wl2[j * WH];
        const uint4* wrp = (const uint4*)&g_wr2[j * WH];
        uint4 wlA = wlp[0], wlB = wlp[1];
        uint4 wrA = wrp[0], wrB = wrp[1];
        int np = (cnt > 0) ? (32 - __clz(cnt)) : 0;
        int CW = 0;
        for (int p = 0; p < np; p++) {
            const uint4* ap = (const uint4*)&sa[p * WH];
            uint4 aA = ap[0], aB = ap[1];
            int s = __popc(aA.x & wlA.x) + __popc(aA.y & wlA.y) +
                    __popc(aA.z & wlA.z) + __popc(aA.w & wlA.w) +
                    __popc(aB.x & wlB.x) + __popc(aB.y & wlB.y) +
                    __popc(aB.z & wlB.z) + __popc(aB.w & wlB.w);
            CW += (2 * s - sPA[p]) * (1 << p);
        }
        const uint4* xp = (const uint4*)sx;
        uint4 xA = xp[0], xB = xp[1];
        int x2 = __popc(xA.x ^ wrA.x) + __popc(xA.y ^ wrA.y) +
                 __popc(xA.z ^ wrA.z) + __popc(xA.w ^ wrA.w) +
                 __popc(xB.x ^ wrB.x) + __popc(xB.y ^ wrB.y) +
                 __popc(xB.z ^ wrB.z) + __popc(xB.w ^ wrB.w);
        int dot2 = FH - 2 * x2;
        float rc = (cnt > 0) ? (1.f / (float)cnt) : 1.f;
        float v = (float)(2 * CW - cnt * g_ws2[j]) * rc * g_al2[j]
                + (float)dot2 * g_ar2[j] + b2[j];
        vals[j] = v;
    }
    __syncthreads();
    if (tid == 0) {
        float m = vals[0];
        for (int k = 1; k < FOUT; k++) m = fmaxf(m, vals[k]);
        float se = 0.f;
        for (int k = 0; k < FOUT; k++) se += expf(vals[k] - m);
        slse = m + logf(se);
    }
    __syncthreads();
    if (tid < FOUT) out[i * FOUT + tid] = vals[tid] - slse;
}

// ---------------- host launcher ----------------
extern "C" void kernel_launch(void* const* d_in, const int* in_sizes, int n_in,
                              void* d_out, int out_size) {
    const float* x = nullptr;
    const void *ei1 = nullptr, *ei2 = nullptr;
    const float *W1l = nullptr, *W1r = nullptr, *b1 = nullptr;
    const float *W2l = nullptr, *W2r = nullptr, *b2 = nullptr;
    int c1 = 0, c2 = 0;
    for (int i = 0; i < n_in; i++) {
        switch (in_sizes[i]) {
            case 176304128: x   = (const float*)d_in[i]; break;
            case 563200:    ei1 = d_in[i]; break;
            case 20480:     ei2 = d_in[i]; break;
            case 154112:    if (c1++ == 0) W1l = (const float*)d_in[i];
                            else           W1r = (const float*)d_in[i]; break;
            case 256:       b1  = (const float*)d_in[i]; break;
            case 10496:     if (c2++ == 0) W2l = (const float*)d_in[i];
                            else           W2r = (const float*)d_in[i]; break;
            case 41:        b2  = (const float*)d_in[i]; break;
            default: break; // n1 / n_batch scalars
        }
    }

    k_init<<<(N1V + 255) / 256, 256>>>(ei1);          // 0
    k_hist<<<(E1V + 255) / 256, 256>>>(ei1, ei2);     // 1
    k_weights<<<75, 256>>>(W1l, W1r, W2l, W2r);       // 2
    k_bin<<<N0 / 8, 256>>>(x);                        // 3
    k_scan<<<2, 1024>>>();                            // 4
    k_scatter<<<(E1V + 255) / 256, 256>>>(ei1, ei2);  // 5
    k_agg1<<<N1V / 8, 256>>>();                       // 6
    k_gemm1<<<N1V / RPB1, 256>>>(b1);                 // 7
    k_l2<<<NBV, 64>>>(b2, (float*)d_out);             // 8
}

// round 5
// speedup vs baseline: 1.1993x; 1.0759x over previous
#include <cuda_runtime.h>
#include <stdint.h>

#define N0   292864
#define N1V  11264
#define NBV  1024
#define FIN  602
#define FH   256
#define FOUT 41
#define E1V  281600
#define E2V  10240
#define WIN  19   // 32-bit words holding 602 bits
#define WSTR 20   // padded stride (word 19 == 0)
#define WH   8    // words for 256 bits
#define NPL  7    // bit planes (counts <= 127)

// ---------------- device scratch (static, allocation-free) ----------------
static __device__ __align__(16) uint32_t g_xb [(size_t)N0  * WSTR];      // 23.4 MB
static __device__ __align__(16) uint32_t g_pl1[(size_t)N1V * NPL * WSTR];// 6.3 MB
static __device__ int      g_PA1[N1V * NPL];
static __device__ __align__(16) uint32_t g_hb [N1V * WH];
static __device__ int g_deg1[N1V], g_off1[N1V + 1], g_cur1[N1V];
static __device__ int g_deg2[NBV], g_off2[NBV + 1], g_cur2[NBV];
static __device__ int g_csr1[E1V], g_csr2[E2V];
static __device__ unsigned char g_mask[N0];   // zero-init at load; hist only sets 1s (idempotent)
static __device__ __align__(16) uint32_t g_wl1[FH * WSTR], g_wr1[FH * WSTR];
static __device__ float g_al1[FH], g_ar1[FH];
static __device__ int   g_ws1[FH];
static __device__ __align__(16) uint32_t g_wl2[FOUT * WH], g_wr2[FOUT * WH];
static __device__ float g_al2[FOUT], g_ar2[FOUT];
static __device__ int   g_ws2[FOUT];
static __device__ int g_is64;

// edge-index accessor: metadata may serialize int64 as int64 or (x64-off) int32
static __device__ __forceinline__ int eget(const void* p, long long i) {
    return g_is64 ? (int)((const long long*)p)[i] : ((const int*)p)[i];
}

// ripple-carry add of a 1-bit addend into 7 bit-planes
#define RIPPLE(c) do { uint32_t t_;            \
    t_ = p0 & (c); p0 ^= (c); (c) = t_;        \
    t_ = p1 & (c); p1 ^= (c); (c) = t_;        \
    t_ = p2 & (c); p2 ^= (c); (c) = t_;        \
    t_ = p3 & (c); p3 ^= (c); (c) = t_;        \
    t_ = p4 & (c); p4 ^= (c); (c) = t_;        \
    t_ = p5 & (c); p5 ^= (c); (c) = t_;        \
    p6 ^= (c); } while (0)

// ---------------- kernels ----------------

// zero degree arrays + detect edge dtype (mask needs no zeroing: zero-init + idempotent)
__global__ void k_init(const void* ei1) {
    int i = blockIdx.x * blockDim.x + threadIdx.x;
    if (i < N1V) g_deg1[i] = 0;
    if (i < NBV) g_deg2[i] = 0;
    if (i == 0) {
        const unsigned* u = (const unsigned*)ei1;
        int z = 0;
        for (int k = 0; k < 16; k++) z += (u[2 * k + 1] == 0u) ? 1 : 0;
        g_is64 = (z == 16) ? 1 : 0;   // int64 values < 2^31 -> high words all zero
    }
}

__global__ void k_hist(const void* ei1, const void* ei2) {
    int e = blockIdx.x * blockDim.x + threadIdx.x;
    if (e < E1V) {
        int d = eget(ei1, (long long)E1V + e);
        atomicAdd(&g_deg1[d], 1);
        int s = eget(ei1, e);
        g_mask[s] = 1;
    }
    if (e < E2V) {
        int d = eget(ei2, (long long)E2V + e);
        atomicAdd(&g_deg2[d], 1);
    }
}

__global__ void k_weights(const float* __restrict__ W1l, const float* __restrict__ W1r,
                          const float* __restrict__ W2l, const float* __restrict__ W2r) {
    int gw   = (blockIdx.x * blockDim.x + threadIdx.x) >> 5;
    int lane = threadIdx.x & 31;
    if (gw < 2 * FH) {
        const float* W  = (gw < FH) ? W1l : W1r;
        uint32_t*    WB = (gw < FH) ? g_wl1 : g_wr1;
        float*       AL = (gw < FH) ? g_al1 : g_ar1;
        int j = (gw < FH) ? gw : gw - FH;
        float asum = 0.f; int pos = 0;
        for (int k = 0; k < WIN; k++) {
            int f = k * 32 + lane;
            float w = (f < FIN) ? W[j * FIN + f] : 0.f;
            bool p = (f < FIN) && (w > 0.f);
            uint32_t b = __ballot_sync(0xffffffffu, p);
            if (lane == 0) WB[j * WSTR + k] = b;
            asum += fabsf(w);
            pos  += p ? 1 : 0;
        }
        if (lane == 0) WB[j * WSTR + WIN] = 0u;
        for (int o = 16; o; o >>= 1) asum += __shfl_xor_sync(0xffffffffu, asum, o);
        pos = __reduce_add_sync(0xffffffffu, pos);
        if (lane == 0) {
            AL[j] = asum / (float)FIN;
            if (gw < FH) g_ws1[j] = 2 * pos - FIN;
        }
    } else if (gw < 2 * FH + 2 * FOUT) {
        int g2 = gw - 2 * FH;
        const float* W  = (g2 < FOUT) ? W2l : W2r;
        uint32_t*    WB = (g2 < FOUT) ? g_wl2 : g_wr2;
        float*       AL = (g2 < FOUT) ? g_al2 : g_ar2;
        int j = (g2 < FOUT) ? g2 : g2 - FOUT;
        float asum = 0.f; int pos = 0;
        for (int k = 0; k < WH; k++) {
            int f = k * 32 + lane;
            float w = W[j * FH + f];
            bool p = (w > 0.f);
            uint32_t b = __ballot_sync(0xffffffffu, p);
            if (lane == 0) WB[j * WH + k] = b;
            asum += fabsf(w);
            pos  += p ? 1 : 0;
        }
        for (int o = 16; o; o >>= 1) asum += __shfl_xor_sync(0xffffffffu, asum, o);
        pos = __reduce_add_sync(0xffffffffu, pos);
        if (lane == 0) {
            AL[j] = asum / (float)FH;
            if (g2 < FOUT) g_ws2[j] = 2 * pos - FH;
        }
    }
}

// per-row mean + sign + bitpack; skip rows never used downstream.
// __ldcs: x is single-use streaming data -> don't evict g_xb from L2.
__global__ __launch_bounds__(256) void k_bin(const float* __restrict__ x) {
    int wid = threadIdx.x >> 5, lane = threadIdx.x & 31;
    int row = blockIdx.x * 8 + wid;
    bool need = (row < N1V) || (g_mask[row] != 0);
    if (!need) return;
    const float* xr = x + (size_t)row * FIN;
    float v[WIN]; float s = 0.f;
#pragma unroll
    for (int k = 0; k < WIN; k++) {
        int f = k * 32 + lane;
        float val = (f < FIN) ? __ldcs(xr + f) : 0.f;
        v[k] = val; s += val;
    }
    for (int o = 16; o; o >>= 1) s += __shfl_xor_sync(0xffffffffu, s, o);
    float mean = s * (1.f / (float)FIN);
    uint32_t myw = 0;
#pragma unroll
    for (int k = 0; k < WIN; k++) {
        uint32_t b = __ballot_sync(0xffffffffu, ((k * 32 + lane) < FIN) && (v[k] > mean));
        if (lane == k) myw = b;
    }
    if (lane < WSTR) g_xb[(size_t)row * WSTR + lane] = (lane < WIN) ? myw : 0u;
}

// both prefix scans in one launch (block 0: layer1, block 1: layer2)
__global__ void k_scan() {
    __shared__ int sm[1024];
    int t = threadIdx.x;
    if (blockIdx.x == 0) {                 // N1V = 1024 * 11
        int loc[11]; int s = 0;
#pragma unroll
        for (int k = 0; k < 11; k++) { loc[k] = s; s += g_deg1[t * 11 + k]; }
        sm[t] = s; __syncthreads();
        for (int o = 1; o < 1024; o <<= 1) {
            int v = (t >= o) ? sm[t - o] : 0; __syncthreads();
            sm[t] += v; __syncthreads();
        }
        int ex = (t > 0) ? sm[t - 1] : 0;
#pragma unroll
        for (int k = 0; k < 11; k++) {
            g_off1[t * 11 + k] = ex + loc[k];
            g_cur1[t * 11 + k] = ex + loc[k];
        }
        if (t == 1023) g_off1[N1V] = sm[1023];
    } else {                               // NBV = 1024
        int s = g_deg2[t];
        sm[t] = s; __syncthreads();
        for (int o = 1; o < 1024; o <<= 1) {
            int v = (t >= o) ? sm[t - o] : 0; __syncthreads();
            sm[t] += v; __syncthreads();
        }
        int ex = (t > 0) ? sm[t - 1] : 0;
        g_off2[t] = ex; g_cur2[t] = ex;
        if (t == 1023) g_off2[NBV] = sm[1023];
    }
}

__global__ void k_scatter(const void* ei1, const void* ei2) {
    int e = blockIdx.x * blockDim.x + threadIdx.x;
    if (e < E1V) {
        int d = eget(ei1, (long long)E1V + e);
        int s = eget(ei1, e);
        int p = atomicAdd(&g_cur1[d], 1);
        g_csr1[p] = s;
    }
    if (e < E2V) {
        int d = eget(ei2, (long long)E2V + e);
        int s = eget(ei2, e);
        int p = atomicAdd(&g_cur2[d], 1);
        g_csr2[p] = s;
    }
}

// bit-sliced (ripple-carry) per-feature edge-count accumulation, layer 1
// 4x edge unroll: 4 independent gathers in flight per warp
__global__ __launch_bounds__(256) void k_agg1() {
    int gw   = (blockIdx.x * blockDim.x + threadIdx.x) >> 5;
    int lane = threadIdx.x & 31;
    if (gw >= N1V) return;
    int beg = g_off1[gw], d = g_deg1[gw];
    uint32_t p0 = 0, p1 = 0, p2 = 0, p3 = 0, p4 = 0, p5 = 0, p6 = 0;
    bool act = (lane < WSTR);
    int e = 0;
    for (; e + 4 <= d; e += 4) {
        int s0 = __ldg(&g_csr1[beg + e + 0]);
        int s1 = __ldg(&g_csr1[beg + e + 1]);
        int s2 = __ldg(&g_csr1[beg + e + 2]);
        int s3 = __ldg(&g_csr1[beg + e + 3]);
        uint32_t c0 = act ? __ldg(&g_xb[(size_t)s0 * WSTR + lane]) : 0u;
        uint32_t c1 = act ? __ldg(&g_xb[(size_t)s1 * WSTR + lane]) : 0u;
        uint32_t c2 = act ? __ldg(&g_xb[(size_t)s2 * WSTR + lane]) : 0u;
        uint32_t c3 = act ? __ldg(&g_xb[(size_t)s3 * WSTR + lane]) : 0u;
        RIPPLE(c0); RIPPLE(c1); RIPPLE(c2); RIPPLE(c3);
    }
    for (; e < d; e++) {
        int s = __ldg(&g_csr1[beg + e]);
        uint32_t c = act ? __ldg(&g_xb[(size_t)s * WSTR + lane]) : 0u;
        RIPPLE(c);
    }
    size_t base = (size_t)gw * NPL * WSTR;
    if (act) {
        g_pl1[base + 0 * WSTR + lane] = p0;
        g_pl1[base + 1 * WSTR + lane] = p1;
        g_pl1[base + 2 * WSTR + lane] = p2;
        g_pl1[base + 3 * WSTR + lane] = p3;
        g_pl1[base + 4 * WSTR + lane] = p4;
        g_pl1[base + 5 * WSTR + lane] = p5;
        g_pl1[base + 6 * WSTR + lane] = p6;
    }
    int pa;
    pa = __reduce_add_sync(0xffffffffu, __popc(p0)); if (!lane) g_PA1[gw * NPL + 0] = pa;
    pa = __reduce_add_sync(0xffffffffu, __popc(p1)); if (!lane) g_PA1[gw * NPL + 1] = pa;
    pa = __reduce_add_sync(0xffffffffu, __popc(p2)); if (!lane) g_PA1[gw * NPL + 2] = pa;
    pa = __reduce_add_sync(0xffffffffu, __popc(p3)); if (!lane) g_PA1[gw * NPL + 3] = pa;
    pa = __reduce_add_sync(0xffffffffu, __popc(p4)); if (!lane) g_PA1[gw * NPL + 4] = pa;
    pa = __reduce_add_sync(0xffffffffu, __popc(p5)); if (!lane) g_PA1[gw * NPL + 5] = pa;
    pa = __reduce_add_sync(0xffffffffu, __popc(p6)); if (!lane) g_PA1[gw * NPL + 6] = pa;
}

#define RPB1 16
// layer-1 popcount GEMM + bias + relu + row-mean binarize -> g_hb
__global__ __launch_bounds__(256) void k_gemm1(const float* __restrict__ b1) {
    int tid = threadIdx.x, lane = tid & 31, wid = tid >> 5;
    __shared__ __align__(16) uint32_t sa[NPL * WSTR];
    __shared__ __align__(16) uint32_t sx[WSTR];
    __shared__ int sPA[NPL];
    __shared__ int scnt;
    __shared__ float sred[8];

    uint4 wl4[5], wr4[5];
    const uint4* wlp = (const uint4*)&g_wl1[tid * WSTR];
    const uint4* wrp = (const uint4*)&g_wr1[tid * WSTR];
#pragma unroll
    for (int q = 0; q < 5; q++) { wl4[q] = wlp[q]; wr4[q] = wrp[q]; }
    float al = g_al1[tid], ar = g_ar1[tid], bb = b1[tid];
    int wsum = g_ws1[tid];

    for (int r = 0; r < RPB1; r++) {
        int i = blockIdx.x * RPB1 + r;
        for (int idx = tid; idx < NPL * WSTR; idx += 256)
            sa[idx] = g_pl1[(size_t)i * NPL * WSTR + idx];
        if (tid < WSTR) sx[tid] = g_xb[(size_t)i * WSTR + tid];
        if (tid < NPL)  sPA[tid] = g_PA1[i * NPL + tid];
        if (tid == 255) scnt = g_deg1[i];
        __syncthreads();

        int cnt = scnt;
        int np = (cnt > 0) ? (32 - __clz(cnt)) : 0;
        int CW = 0;
        for (int p = 0; p < np; p++) {
            const uint4* ap = (const uint4*)&sa[p * WSTR];
            int s = 0;
#pragma unroll
            for (int q = 0; q < 5; q++) {
                uint4 a = ap[q]; uint4 w = wl4[q];
                s += __popc(a.x & w.x) + __popc(a.y & w.y) +
                     __popc(a.z & w.z) + __popc(a.w & w.w);
            }
            CW += (2 * s - sPA[p]) * (1 << p);
        }
        int x2 = 0;
        const uint4* xp = (const uint4*)sx;
#pragma unroll
        for (int q = 0; q < 5; q++) {
            uint4 a = xp[q]; uint4 w = wr4[q];
            x2 += __popc(a.x ^ w.x) + __popc(a.y ^ w.y) +
                  __popc(a.z ^ w.z) + __popc(a.w ^ w.w);
        }
        int dot2 = FIN - 2 * x2;
        float rc = (cnt > 0) ? (1.f / (float)cnt) : 1.f;
        float h = (float)(2 * CW - cnt * wsum) * rc * al + (float)dot2 * ar + bb;
        h = fmaxf(h, 0.f);

        float s2 = h;
        for (int o = 16; o; o >>= 1) s2 += __shfl_xor_sync(0xffffffffu, s2, o);
        if (lane == 0) sred[wid] = s2;
        __syncthreads();
        float tot = 0.f;
#pragma unroll
        for (int k = 0; k < 8; k++) tot += sred[k];
        float mean = tot * (1.f / (float)FH);
        uint32_t bits = __ballot_sync(0xffffffffu, h > mean);
        if (lane == 0) g_hb[i * WH + wid] = bits;
        __syncthreads();
    }
}

// fused layer 2: warp 0 aggregates edges (bit-sliced), then 64 threads do
// popcount GEMM + bias + log_softmax. One block per target row.
__global__ __launch_bounds__(64) void k_l2(const float* __restrict__ b2,
                                           float* __restrict__ out) {
    int i = blockIdx.x, tid = threadIdx.x;
    __shared__ __align__(16) uint32_t sa[NPL * WH];
    __shared__ __align__(16) uint32_t sx[WH];
    __shared__ int sPA[NPL];
    __shared__ float vals[FOUT];
    __shared__ float slse;

    int cnt = g_deg2[i];
    if (tid < WH) sx[tid] = g_hb[(size_t)i * WH + tid];

    if (tid < 32) {               // warp 0: bit-sliced aggregation
        int lane = tid;
        int beg = g_off2[i];
        uint32_t p0 = 0, p1 = 0, p2 = 0, p3 = 0, p4 = 0, p5 = 0, p6 = 0;
        bool act = (lane < WH);
        int e = 0;
        for (; e + 4 <= cnt; e += 4) {
            int s0 = __ldg(&g_csr2[beg + e + 0]);
            int s1 = __ldg(&g_csr2[beg + e + 1]);
            int s2 = __ldg(&g_csr2[beg + e + 2]);
            int s3 = __ldg(&g_csr2[beg + e + 3]);
            uint32_t c0 = act ? __ldg(&g_hb[(size_t)s0 * WH + lane]) : 0u;
            uint32_t c1 = act ? __ldg(&g_hb[(size_t)s1 * WH + lane]) : 0u;
            uint32_t c2 = act ? __ldg(&g_hb[(size_t)s2 * WH + lane]) : 0u;
            uint32_t c3 = act ? __ldg(&g_hb[(size_t)s3 * WH + lane]) : 0u;
            RIPPLE(c0); RIPPLE(c1); RIPPLE(c2); RIPPLE(c3);
        }
        for (; e < cnt; e++) {
            int s = __ldg(&g_csr2[beg + e]);
            uint32_t c = act ? __ldg(&g_hb[(size_t)s * WH + lane]) : 0u;
            RIPPLE(c);
        }
        if (act) {
            sa[0 * WH + lane] = p0; sa[1 * WH + lane] = p1;
            sa[2 * WH + lane] = p2; sa[3 * WH + lane] = p3;
            sa[4 * WH + lane] = p4; sa[5 * WH + lane] = p5;
            sa[6 * WH + lane] = p6;
        }
        int pa;
        pa = __reduce_add_sync(0xffffffffu, __popc(p0)); if (!lane) sPA[0] = pa;
        pa = __reduce_add_sync(0xffffffffu, __popc(p1)); if (!lane) sPA[1] = pa;
        pa = __reduce_add_sync(0xffffffffu, __popc(p2)); if (!lane) sPA[2] = pa;
        pa = __reduce_add_sync(0xffffffffu, __popc(p3)); if (!lane) sPA[3] = pa;
        pa = __reduce_add_sync(0xffffffffu, __popc(p4)); if (!lane) sPA[4] = pa;
        pa = __reduce_add_sync(0xffffffffu, __popc(p5)); if (!lane) sPA[5] = pa;
        pa = __reduce_add_sync(0xffffffffu, __popc(p6)); if (!lane) sPA[6] = pa;
    }
    __syncthreads();

    if (tid < FOUT) {
        int j = tid;
        const uint4* wlp = (const uint4*)&g_wl2[j * WH];
        const uint4* wrp = (const uint4*)&g_wr2[j * WH];
        uint4 wlA = wlp[0], wlB = wlp[1];
        uint4 wrA = wrp[0], wrB = wrp[1];
        int np = (cnt > 0) ? (32 - __clz(cnt)) : 0;
        int CW = 0;
        for (int p = 0; p < np; p++) {
            const uint4* ap = (const uint4*)&sa[p * WH];
            uint4 aA = ap[0], aB = ap[1];
            int s = __popc(aA.x & wlA.x) + __popc(aA.y & wlA.y) +
                    __popc(aA.z & wlA.z) + __popc(aA.w & wlA.w) +
                    __popc(aB.x & wlB.x) + __popc(aB.y & wlB.y) +
                    __popc(aB.z & wlB.z) + __popc(aB.w & wlB.w);
            CW += (2 * s - sPA[p]) * (1 << p);
        }
        const uint4* xp = (const uint4*)sx;
        uint4 xA = xp[0], xB = xp[1];
        int x2 = __popc(xA.x ^ wrA.x) + __popc(xA.y ^ wrA.y) +
                 __popc(xA.z ^ wrA.z) + __popc(xA.w ^ wrA.w) +
                 __popc(xB.x ^ wrB.x) + __popc(xB.y ^ wrB.y) +
                 __popc(xB.z ^ wrB.z) + __popc(xB.w ^ wrB.w);
        int dot2 = FH - 2 * x2;
        float rc = (cnt > 0) ? (1.f / (float)cnt) : 1.f;
        float v = (float)(2 * CW - cnt * g_ws2[j]) * rc * g_al2[j]
                + (float)dot2 * g_ar2[j] + b2[j];
        vals[j] = v;
    }
    __syncthreads();
    if (tid == 0) {
        float m = vals[0];
        for (int k = 1; k < FOUT; k++) m = fmaxf(m, vals[k]);
        float se = 0.f;
        for (int k = 0; k < FOUT; k++) se += expf(vals[k] - m);
        slse = m + logf(se);
    }
    __syncthreads();
    if (tid < FOUT) out[i * FOUT + tid] = vals[tid] - slse;
}

// ---------------- host launcher (stream fork/join inside graph capture) ----
extern "C" void kernel_launch(void* const* d_in, const int* in_sizes, int n_in,
                              void* d_out, int out_size) {
    const float* x = nullptr;
    const void *ei1 = nullptr, *ei2 = nullptr;
    const float *W1l = nullptr, *W1r = nullptr, *b1 = nullptr;
    const float *W2l = nullptr, *W2r = nullptr, *b2 = nullptr;
    int c1 = 0, c2 = 0;
    for (int i = 0; i < n_in; i++) {
        switch (in_sizes[i]) {
            case 176304128: x   = (const float*)d_in[i]; break;
            case 563200:    ei1 = d_in[i]; break;
            case 20480:     ei2 = d_in[i]; break;
            case 154112:    if (c1++ == 0) W1l = (const float*)d_in[i];
                            else           W1r = (const float*)d_in[i]; break;
            case 256:       b1  = (const float*)d_in[i]; break;
            case 10496:     if (c2++ == 0) W2l = (const float*)d_in[i];
                            else           W2r = (const float*)d_in[i]; break;
            case 41:        b2  = (const float*)d_in[i]; break;
            default: break; // n1 / n_batch scalars
        }
    }

    // streams/events created once on the pre-capture correctness call
    static cudaStream_t sCsr = nullptr, sW = nullptr;
    static cudaEvent_t evStart = nullptr, evHist = nullptr, evCsr = nullptr, evW = nullptr;
    if (!sCsr) {
        cudaStreamCreateWithFlags(&sCsr, cudaStreamNonBlocking);
        cudaStreamCreateWithFlags(&sW,   cudaStreamNonBlocking);
        cudaEventCreateWithFlags(&evStart, cudaEventDisableTiming);
        cudaEventCreateWithFlags(&evHist,  cudaEventDisableTiming);
        cudaEventCreateWithFlags(&evCsr,   cudaEventDisableTiming);
        cudaEventCreateWithFlags(&evW,     cudaEventDisableTiming);
    }
    cudaStream_t m = 0;  // same default stream the <<<>>> launches use

    // weights branch: independent of everything on the main chain
    cudaEventRecord(evStart, m);
    cudaStreamWaitEvent(sW, evStart, 0);
    k_weights<<<75, 256, 0, sW>>>(W1l, W1r, W2l, W2r);
    cudaEventRecord(evW, sW);

    // main: init -> hist (produces mask + degrees)
    k_init<<<(N1V + 255) / 256, 256, 0, m>>>(ei1);
    k_hist<<<(E1V + 255) / 256, 256, 0, m>>>(ei1, ei2);
    cudaEventRecord(evHist, m);

    // CSR branch (scan+scatter) runs concurrently with the 73us DRAM-bound k_bin
    cudaStreamWaitEvent(sCsr, evHist, 0);
    k_scan<<<2, 1024, 0, sCsr>>>();
    k_scatter<<<(E1V + 255) / 256, 256, 0, sCsr>>>(ei1, ei2);
    cudaEventRecord(evCsr, sCsr);

    k_bin<<<N0 / 8, 256, 0, m>>>(x);

    // join: agg1 needs bin + CSR; gemm1 additionally needs weights
    cudaStreamWaitEvent(m, evCsr, 0);
    k_agg1<<<N1V / 8, 256, 0, m>>>();
    cudaStreamWaitEvent(m, evW, 0);
    k_gemm1<<<N1V / RPB1, 256, 0, m>>>(b1);
    k_l2<<<NBV, 64, 0, m>>>(b2, (float*)d_out);
}

// round 8
// speedup vs baseline: 1.3403x; 1.1175x over previous
#include <cuda_runtime.h>
#include <stdint.h>

#define N0   292864
#define N1V  11264
#define NBV  1024
#define FIN  602
#define FH   256
#define FOUT 41
#define E1V  281600
#define E2V  10240
#define WIN  19    // 32-bit words holding 602 bits
#define WSTR 20    // padded stride (word 19 == 0)
#define WH   8     // words for 256 bits
#define NPL  7     // bit planes (counts <= 127)
#define KA   1216  // A/B K dim: [0,608) = cnt part, [608,1216) = self-sign part

// ---------------- device scratch (static, allocation-free) ----------------
static __device__ __align__(16) uint32_t g_xb [(size_t)N0  * WSTR];   // 23.4 MB
static __device__ __align__(16) int8_t   g_cA [(size_t)N1V * KA];     // 13.7 MB
static __device__ __align__(16) int8_t   g_sw [(size_t)FH  * KA];     // 311 KB
static __device__ __align__(16) uint32_t g_hb [N1V * WH];
static __device__ int g_deg1[N1V], g_off1[N1V + 1], g_cur1[N1V];
static __device__ int g_deg2[NBV], g_off2[NBV + 1], g_cur2[NBV];
static __device__ int g_csr1[E1V], g_csr2[E2V];
static __device__ unsigned char g_mask[N0];   // zero-init at load; hist only sets 1s
static __device__ float g_al1[FH], g_ar1[FH];
static __device__ int   g_ws1[FH];
static __device__ __align__(16) uint32_t g_wl2[FOUT * WH], g_wr2[FOUT * WH];
static __device__ float g_al2[FOUT], g_ar2[FOUT];
static __device__ int   g_ws2[FOUT];
static __device__ int g_is64;

static __device__ __forceinline__ int eget(const void* p, long long i) {
    return g_is64 ? (int)((const long long*)p)[i] : ((const int*)p)[i];
}

// ripple-carry add of a 1-bit addend into 7 bit-planes
#define RIPPLE(c) do { uint32_t t_;            \
    t_ = p0 & (c); p0 ^= (c); (c) = t_;        \
    t_ = p1 & (c); p1 ^= (c); (c) = t_;        \
    t_ = p2 & (c); p2 ^= (c); (c) = t_;        \
    t_ = p3 & (c); p3 ^= (c); (c) = t_;        \
    t_ = p4 & (c); p4 ^= (c); (c) = t_;        \
    t_ = p5 & (c); p5 ^= (c); (c) = t_;        \
    p6 ^= (c); } while (0)

// spread low 4 bits of n into bytes 0..3 (bit i -> byte i, value 0/1).
// MUST mask to 4 bits: bit b lands at {b, b+7, b+14, b+21}; unmasked high
// bits (8,9,16,...) alias into the kept positions {0,8,16,24}.  (R7 bug)
static __device__ __forceinline__ uint32_t spread4(uint32_t n) {
    return ((n & 0xFu) * 0x00204081u) & 0x01010101u;
}

#define MMA_S8(c, A0, A1, A2, A3, B0, B1)                                   \
    asm volatile("mma.sync.aligned.m16n8k32.row.col.s32.s8.s8.s32 "         \
        "{%0,%1,%2,%3}, {%4,%5,%6,%7}, {%8,%9}, {%0,%1,%2,%3};"             \
        : "+r"(c[0]), "+r"(c[1]), "+r"(c[2]), "+r"(c[3])                    \
        : "r"(A0), "r"(A1), "r"(A2), "r"(A3), "r"(B0), "r"(B1))

// ---------------- kernels ----------------

__global__ void k_init(const void* ei1) {
    int i = blockIdx.x * blockDim.x + threadIdx.x;
    if (i < N1V) g_deg1[i] = 0;
    if (i < NBV) g_deg2[i] = 0;
    if (i == 0) {
        const unsigned* u = (const unsigned*)ei1;
        int z = 0;
        for (int k = 0; k < 16; k++) z += (u[2 * k + 1] == 0u) ? 1 : 0;
        g_is64 = (z == 16) ? 1 : 0;
    }
}

__global__ void k_hist(const void* ei1, const void* ei2) {
    int e = blockIdx.x * blockDim.x + threadIdx.x;
    if (e < E1V) {
        int d = eget(ei1, (long long)E1V + e);
        atomicAdd(&g_deg1[d], 1);
        int s = eget(ei1, e);
        g_mask[s] = 1;
    }
    if (e < E2V) {
        int d = eget(ei2, (long long)E2V + e);
        atomicAdd(&g_deg2[d], 1);
    }
}

// layer-1: alpha/wsum + int8 sign matrix g_sw[n][k];  layer-2: bit weights
__global__ void k_weights(const float* __restrict__ W1l, const float* __restrict__ W1r,
                          const float* __restrict__ W2l, const float* __restrict__ W2r) {
    int gw   = (blockIdx.x * blockDim.x + threadIdx.x) >> 5;
    int lane = threadIdx.x & 31;
    if (gw < 2 * FH) {
        const float* W  = (gw < FH) ? W1l : W1r;
        float*       AL = (gw < FH) ? g_al1 : g_ar1;
        int j    = (gw < FH) ? gw : gw - FH;
        int koff = (gw < FH) ? 0 : 608;
        float asum = 0.f; int pos = 0;
        for (int k = 0; k < WIN; k++) {
            int f = k * 32 + lane;
            float w = (f < FIN) ? W[j * FIN + f] : 0.f;
            bool p = (f < FIN) && (w > 0.f);
            if (f < FIN) g_sw[(size_t)j * KA + koff + f] = p ? (int8_t)1 : (int8_t)-1;
            asum += fabsf(w);
            pos  += p ? 1 : 0;
        }
        if (lane < 6) g_sw[(size_t)j * KA + koff + FIN + lane] = 0;  // pad
        for (int o = 16; o; o >>= 1) asum += __shfl_xor_sync(0xffffffffu, asum, o);
        pos = __reduce_add_sync(0xffffffffu, pos);
        if (lane == 0) {
            AL[j] = asum / (float)FIN;
            if (gw < FH) g_ws1[j] = 2 * pos - FIN;
        }
    } else if (gw < 2 * FH + 2 * FOUT) {
        int g2 = gw - 2 * FH;
        const float* W  = (g2 < FOUT) ? W2l : W2r;
        uint32_t*    WB = (g2 < FOUT) ? g_wl2 : g_wr2;
        float*       AL = (g2 < FOUT) ? g_al2 : g_ar2;
        int j = (g2 < FOUT) ? g2 : g2 - FOUT;
        float asum = 0.f; int pos = 0;
        for (int k = 0; k < WH; k++) {
            int f = k * 32 + lane;
            float w = W[j * FH + f];
            bool p = (w > 0.f);
            uint32_t b = __ballot_sync(0xffffffffu, p);
            if (lane == 0) WB[j * WH + k] = b;
            asum += fabsf(w);
            pos  += p ? 1 : 0;
        }
        for (int o = 16; o; o >>= 1) asum += __shfl_xor_sync(0xffffffffu, asum, o);
        pos = __reduce_add_sync(0xffffffffu, pos);
        if (lane == 0) {
            AL[j] = asum / (float)FH;
            if (g2 < FOUT) g_ws2[j] = 2 * pos - FH;
        }
    }
}

// per-row mean + sign + bitpack; skip rows never used downstream
__global__ __launch_bounds__(256) void k_bin(const float* __restrict__ x) {
    int wid = threadIdx.x >> 5, lane = threadIdx.x & 31;
    int row = blockIdx.x * 8 + wid;
    bool need = (row < N1V) || (g_mask[row] != 0);
    if (!need) return;
    const float* xr = x + (size_t)row * FIN;
    float v[WIN]; float s = 0.f;
#pragma unroll
    for (int k = 0; k < WIN; k++) {
        int f = k * 32 + lane;
        float val = (f < FIN) ? __ldcs(xr + f) : 0.f;
        v[k] = val; s += val;
    }
    for (int o = 16; o; o >>= 1) s += __shfl_xor_sync(0xffffffffu, s, o);
    float mean = s * (1.f / (float)FIN);
    uint32_t myw = 0;
#pragma unroll
    for (int k = 0; k < WIN; k++) {
        uint32_t b = __ballot_sync(0xffffffffu, ((k * 32 + lane) < FIN) && (v[k] > mean));
        if (lane == k) myw = b;
    }
    if (lane < WSTR) g_xb[(size_t)row * WSTR + lane] = (lane < WIN) ? myw : 0u;
}

__global__ void k_scan() {
    __shared__ int sm[1024];
    int t = threadIdx.x;
    if (blockIdx.x == 0) {                 // N1V = 1024 * 11
        int loc[11]; int s = 0;
#pragma unroll
        for (int k = 0; k < 11; k++) { loc[k] = s; s += g_deg1[t * 11 + k]; }
        sm[t] = s; __syncthreads();
        for (int o = 1; o < 1024; o <<= 1) {
            int v = (t >= o) ? sm[t - o] : 0; __syncthreads();
            sm[t] += v; __syncthreads();
        }
        int ex = (t > 0) ? sm[t - 1] : 0;
#pragma unroll
        for (int k = 0; k < 11; k++) {
            g_off1[t * 11 + k] = ex + loc[k];
            g_cur1[t * 11 + k] = ex + loc[k];
        }
        if (t == 1023) g_off1[N1V] = sm[1023];
    } else {                               // NBV = 1024
        int s = g_deg2[t];
        sm[t] = s; __syncthreads();
        for (int o = 1; o < 1024; o <<= 1) {
            int v = (t >= o) ? sm[t - o] : 0; __syncthreads();
            sm[t] += v; __syncthreads();
        }
        int ex = (t > 0) ? sm[t - 1] : 0;
        g_off2[t] = ex; g_cur2[t] = ex;
        if (t == 1023) g_off2[NBV] = sm[1023];
    }
}

__global__ void k_scatter(const void* ei1, const void* ei2) {
    int e = blockIdx.x * blockDim.x + threadIdx.x;
    if (e < E1V) {
        int d = eget(ei1, (long long)E1V + e);
        int s = eget(ei1, e);
        int p = atomicAdd(&g_cur1[d], 1);
        g_csr1[p] = s;
    }
    if (e < E2V) {
        int d = eget(ei2, (long long)E2V + e);
        int s = eget(ei2, e);
        int p = atomicAdd(&g_cur2[d], 1);
        g_csr2[p] = s;
    }
}

// layer-1 edge aggregation: bit-sliced ripple accumulation, then expand the
// 7 bit planes into int8 counts (A cols 0..607) and the target row's sign
// bits into +-1 int8 (A cols 608..1215) for the IMMA GEMM.
__global__ __launch_bounds__(256) void k_agg1() {
    int gw   = (blockIdx.x * blockDim.x + threadIdx.x) >> 5;
    int lane = threadIdx.x & 31;
    if (gw >= N1V) return;
    int beg = g_off1[gw], d = g_deg1[gw];
    uint32_t p0 = 0, p1 = 0, p2 = 0, p3 = 0, p4 = 0, p5 = 0, p6 = 0;
    bool act = (lane < WIN);
    int e = 0;
    for (; e + 4 <= d; e += 4) {
        int s0 = __ldg(&g_csr1[beg + e + 0]);
        int s1 = __ldg(&g_csr1[beg + e + 1]);
        int s2 = __ldg(&g_csr1[beg + e + 2]);
        int s3 = __ldg(&g_csr1[beg + e + 3]);
        uint32_t c0 = act ? __ldg(&g_xb[(size_t)s0 * WSTR + lane]) : 0u;
        uint32_t c1 = act ? __ldg(&g_xb[(size_t)s1 * WSTR + lane]) : 0u;
        uint32_t c2 = act ? __ldg(&g_xb[(size_t)s2 * WSTR + lane]) : 0u;
        uint32_t c3 = act ? __ldg(&g_xb[(size_t)s3 * WSTR + lane]) : 0u;
        RIPPLE(c0); RIPPLE(c1); RIPPLE(c2); RIPPLE(c3);
    }
    for (; e < d; e++) {
        int s = __ldg(&g_csr1[beg + e]);
        uint32_t c = act ? __ldg(&g_xb[(size_t)s * WSTR + lane]) : 0u;
        RIPPLE(c);
    }
    if (act) {
        uint32_t xw = g_xb[(size_t)gw * WSTR + lane];
        uint32_t* outw = (uint32_t*)(g_cA + (size_t)gw * KA);
#pragma unroll
        for (int w = 0; w < 8; w++) {
            uint32_t cw =  spread4(p0 >> (4 * w))
                        | (spread4(p1 >> (4 * w)) << 1)
                        | (spread4(p2 >> (4 * w)) << 2)
                        | (spread4(p3 >> (4 * w)) << 3)
                        | (spread4(p4 >> (4 * w)) << 4)
                        | (spread4(p5 >> (4 * w)) << 5)
                        | (spread4(p6 >> (4 * w)) << 6);
            uint32_t sp = spread4(xw >> (4 * w));
            uint32_t sw = sp | ((sp ^ 0x01010101u) * 0xFFu);  // bit->+1, else -1
            int f0 = lane * 32 + w * 4;
            int vnum = FIN - f0;                               // valid bytes in this word
            uint32_t vm = (vnum >= 4) ? 0xFFFFFFFFu :
                          ((vnum <= 0) ? 0u : ((1u << (8 * vnum)) - 1u));
            outw[lane * 8 + w]       = cw;        // cnt bits already 0 beyond FIN
            outw[152 + lane * 8 + w] = sw & vm;   // mask pad signs to 0
        }
    }
}

// layer-1 GEMM on tensor cores: D = A(11264x1216 s8) x B^T(256x1216 s8),
// split accumulators for the cnt half / self half, fused epilogue
// (scale + bias + relu + row-mean binarize -> g_hb).
__global__ __launch_bounds__(512) void k_gemm1m(const float* __restrict__ bias1) {
    __shared__ float sh[32][257];
    int tid = threadIdx.x, lane = tid & 31, wid = tid >> 5;
    int warp_m = wid & 3, warp_n = wid >> 2;     // 4M x 4N warps
    int g = lane >> 2, t = lane & 3;
    int m0 = blockIdx.x * 64 + warp_m * 16;
    int n0 = warp_n * 64;

    int acc1[8][4], acc2[8][4];
#pragma unroll
    for (int f = 0; f < 8; f++)
#pragma unroll
        for (int i = 0; i < 4; i++) { acc1[f][i] = 0; acc2[f][i] = 0; }

    const int8_t* Ar0 = g_cA + (size_t)(m0 + g) * KA;
    const int8_t* Ar1 = Ar0 + (size_t)8 * KA;

#define K_HALF(ACC, KBASE)                                                      \
    for (int ks = 0; ks < 19; ks++) {                                           \
        int k0 = (KBASE) + ks * 32 + 4 * t;                                     \
        int a0 = *(const int*)(Ar0 + k0);                                       \
        int a1 = *(const int*)(Ar1 + k0);                                       \
        int a2 = *(const int*)(Ar0 + k0 + 16);                                  \
        int a3 = *(const int*)(Ar1 + k0 + 16);                                  \
        _Pragma("unroll")                                                       \
        for (int f = 0; f < 8; f++) {                                           \
            const int8_t* Bp = g_sw + (size_t)(n0 + f * 8 + g) * KA + k0;       \
            int b0 = *(const int*)Bp;                                           \
            int b1 = *(const int*)(Bp + 16);                                    \
            MMA_S8(ACC[f], a0, a1, a2, a3, b0, b1);                             \
        }                                                                       \
    }
    K_HALF(acc1, 0)
    K_HALF(acc2, 608)
#undef K_HALF

    int rg0 = m0 + g;
    int cnt0 = g_deg1[rg0], cnt1 = g_deg1[rg0 + 8];
    float rc0 = cnt0 ? (1.f / (float)cnt0) : 1.f;
    float rc1 = cnt1 ? (1.f / (float)cnt1) : 1.f;

    for (int ph = 0; ph < 2; ph++) {
        if ((warp_m >> 1) == ph) {
            int rl = (warp_m & 1) * 16 + g;
#pragma unroll
            for (int f = 0; f < 8; f++) {
#pragma unroll
                for (int i = 0; i < 4; i++) {
                    int col = n0 + f * 8 + 2 * t + (i & 1);
                    int cnt = (i < 2) ? cnt0 : cnt1;
                    float rc = (i < 2) ? rc0 : rc1;
                    int r = (i < 2) ? rl : rl + 8;
                    float v = g_al1[col] * (float)(2 * acc1[f][i] - cnt * g_ws1[col]) * rc
                            + g_ar1[col] * (float)acc2[f][i] + bias1[col];
                    sh[r][col] = fmaxf(v, 0.f);
                }
            }
        }
        __syncthreads();
        // 16 warps x 2 rows: row-mean + binarize
#pragma unroll
        for (int rr = 0; rr < 2; rr++) {
            int r = wid * 2 + rr;
            float hv[8]; float s = 0.f;
#pragma unroll
            for (int q = 0; q < 8; q++) { hv[q] = sh[r][q * 32 + lane]; s += hv[q]; }
            for (int o = 16; o; o >>= 1) s += __shfl_xor_sync(0xffffffffu, s, o);
            float mean = s * (1.f / (float)FH);
            int grow = blockIdx.x * 64 + ph * 32 + r;
#pragma unroll
            for (int q = 0; q < 8; q++) {
                uint32_t bits = __ballot_sync(0xffffffffu, hv[q] > mean);
                if (lane == q) g_hb[grow * WH + q] = bits;
            }
        }
        __syncthreads();
    }
}

// fused layer 2: warp 0 aggregates edges (bit-sliced), then 64 threads do
// popcount GEMM + bias + log_softmax. One block per target row.
__global__ __launch_bounds__(64) void k_l2(const float* __restrict__ b2,
                                           float* __restrict__ out) {
    int i = blockIdx.x, tid = threadIdx.x;
    __shared__ __align__(16) uint32_t sa[NPL * WH];
    __shared__ __align__(16) uint32_t sx[WH];
    __shared__ int sPA[NPL];
    __shared__ float vals[FOUT];
    __shared__ float slse;

    int cnt = g_deg2[i];
    if (tid < WH) sx[tid] = g_hb[(size_t)i * WH + tid];

    if (tid < 32) {
        int lane = tid;
        int beg = g_off2[i];
        uint32_t p0 = 0, p1 = 0, p2 = 0, p3 = 0, p4 = 0, p5 = 0, p6 = 0;
        bool act = (lane < WH);
        int e = 0;
        for (; e + 4 <= cnt; e += 4) {
            int s0 = __ldg(&g_csr2[beg + e + 0]);
            int s1 = __ldg(&g_csr2[beg + e + 1]);
            int s2 = __ldg(&g_csr2[beg + e + 2]);
            int s3 = __ldg(&g_csr2[beg + e + 3]);
            uint32_t c0 = act ? __ldg(&g_hb[(size_t)s0 * WH + lane]) : 0u;
            uint32_t c1 = act ? __ldg(&g_hb[(size_t)s1 * WH + lane]) : 0u;
            uint32_t c2 = act ? __ldg(&g_hb[(size_t)s2 * WH + lane]) : 0u;
            uint32_t c3 = act ? __ldg(&g_hb[(size_t)s3 * WH + lane]) : 0u;
            RIPPLE(c0); RIPPLE(c1); RIPPLE(c2); RIPPLE(c3);
        }
        for (; e < cnt; e++) {
            int s = __ldg(&g_csr2[beg + e]);
            uint32_t c = act ? __ldg(&g_hb[(size_t)s * WH + lane]) : 0u;
            RIPPLE(c);
        }
        if (act) {
            sa[0 * WH + lane] = p0; sa[1 * WH + lane] = p1;
            sa[2 * WH + lane] = p2; sa[3 * WH + lane] = p3;
            sa[4 * WH + lane] = p4; sa[5 * WH + lane] = p5;
            sa[6 * WH + lane] = p6;
        }
        int pa;
        pa = __reduce_add_sync(0xffffffffu, __popc(p0)); if (!lane) sPA[0] = pa;
        pa = __reduce_add_sync(0xffffffffu, __popc(p1)); if (!lane) sPA[1] = pa;
        pa = __reduce_add_sync(0xffffffffu, __popc(p2)); if (!lane) sPA[2] = pa;
        pa = __reduce_add_sync(0xffffffffu, __popc(p3)); if (!lane) sPA[3] = pa;
        pa = __reduce_add_sync(0xffffffffu, __popc(p4)); if (!lane) sPA[4] = pa;
        pa = __reduce_add_sync(0xffffffffu, __popc(p5)); if (!lane) sPA[5] = pa;
        pa = __reduce_add_sync(0xffffffffu, __popc(p6)); if (!lane) sPA[6] = pa;
    }
    __syncthreads();

    if (tid < FOUT) {
        int j = tid;
        const uint4* wlp = (const uint4*)&g_wl2[j * WH];
        const uint4* wrp = (const uint4*)&g_wr2[j * WH];
        uint4 wlA = wlp[0], wlB = wlp[1];
        uint4 wrA = wrp[0], wrB = wrp[1];
        int np = (cnt > 0) ? (32 - __clz(cnt)) : 0;
        int CW = 0;
        for (int p = 0; p < np; p++) {
            const uint4* ap = (const uint4*)&sa[p * WH];
            uint4 aA = ap[0], aB = ap[1];
            int s = __popc(aA.x & wlA.x) + __popc(aA.y & wlA.y) +
                    __popc(aA.z & wlA.z) + __popc(aA.w & wlA.w) +
                    __popc(aB.x & wlB.x) + __popc(aB.y & wlB.y) +
                    __popc(aB.z & wlB.z) + __popc(aB.w & wlB.w);
            CW += (2 * s - sPA[p]) * (1 << p);
        }
        const uint4* xp = (const uint4*)sx;
        uint4 xA = xp[0], xB = xp[1];
        int x2 = __popc(xA.x ^ wrA.x) + __popc(xA.y ^ wrA.y) +
                 __popc(xA.z ^ wrA.z) + __popc(xA.w ^ wrA.w) +
                 __popc(xB.x ^ wrB.x) + __popc(xB.y ^ wrB.y) +
                 __popc(xB.z ^ wrB.z) + __popc(xB.w ^ wrB.w);
        int dot2 = FH - 2 * x2;
        float rc = (cnt > 0) ? (1.f / (float)cnt) : 1.f;
        float v = (float)(2 * CW - cnt * g_ws2[j]) * rc * g_al2[j]
                + (float)dot2 * g_ar2[j] + b2[j];
        vals[j] = v;
    }
    __syncthreads();
    if (tid == 0) {
        float m = vals[0];
        for (int k = 1; k < FOUT; k++) m = fmaxf(m, vals[k]);
        float se = 0.f;
        for (int k = 0; k < FOUT; k++) se += expf(vals[k] - m);
        slse = m + logf(se);
    }
    __syncthreads();
    if (tid < FOUT) out[i * FOUT + tid] = vals[tid] - slse;
}

// ---------------- host launcher (stream fork/join inside graph capture) ----
extern "C" void kernel_launch(void* const* d_in, const int* in_sizes, int n_in,
                              void* d_out, int out_size) {
    const float* x = nullptr;
    const void *ei1 = nullptr, *ei2 = nullptr;
    const float *W1l = nullptr, *W1r = nullptr, *b1 = nullptr;
    const float *W2l = nullptr, *W2r = nullptr, *b2 = nullptr;
    int c1 = 0, c2 = 0;
    for (int i = 0; i < n_in; i++) {
        switch (in_sizes[i]) {
            case 176304128: x   = (const float*)d_in[i]; break;
            case 563200:    ei1 = d_in[i]; break;
            case 20480:     ei2 = d_in[i]; break;
            case 154112:    if (c1++ == 0) W1l = (const float*)d_in[i];
                            else           W1r = (const float*)d_in[i]; break;
            case 256:       b1  = (const float*)d_in[i]; break;
            case 10496:     if (c2++ == 0) W2l = (const float*)d_in[i];
                            else           W2r = (const float*)d_in[i]; break;
            case 41:        b2  = (const float*)d_in[i]; break;
            default: break;
        }
    }

    static cudaStream_t sCsr = nullptr, sW = nullptr;
    static cudaEvent_t evStart = nullptr, evHist = nullptr, evCsr = nullptr, evW = nullptr;
    if (!sCsr) {
        cudaStreamCreateWithFlags(&sCsr, cudaStreamNonBlocking);
        cudaStreamCreateWithFlags(&sW,   cudaStreamNonBlocking);
        cudaEventCreateWithFlags(&evStart, cudaEventDisableTiming);
        cudaEventCreateWithFlags(&evHist,  cudaEventDisableTiming);
        cudaEventCreateWithFlags(&evCsr,   cudaEventDisableTiming);
        cudaEventCreateWithFlags(&evW,     cudaEventDisableTiming);
    }
    cudaStream_t m = 0;

    cudaEventRecord(evStart, m);
    cudaStreamWaitEvent(sW, evStart, 0);
    k_weights<<<75, 256, 0, sW>>>(W1l, W1r, W2l, W2r);
    cudaEventRecord(evW, sW);

    k_init<<<(N1V + 255) / 256, 256, 0, m>>>(ei1);
    k_hist<<<(E1V + 255) / 256, 256, 0, m>>>(ei1, ei2);
    cudaEventRecord(evHist, m);

    cudaStreamWaitEvent(sCsr, evHist, 0);
    k_scan<<<2, 1024, 0, sCsr>>>();
    k_scatter<<<(E1V + 255) / 256, 256, 0, sCsr>>>(ei1, ei2);
    cudaEventRecord(evCsr, sCsr);

    k_bin<<<N0 / 8, 256, 0, m>>>(x);

    cudaStreamWaitEvent(m, evCsr, 0);
    k_agg1<<<N1V / 8, 256, 0, m>>>();
    cudaStreamWaitEvent(m, evW, 0);
    k_gemm1m<<<N1V / 64, 512, 0, m>>>(b1);
    k_l2<<<NBV, 64, 0, m>>>(b2, (float*)d_out);
}